// round 8
// baseline (speedup 1.0000x reference)
#include <cuda_runtime.h>

// STN bilinear sampler, v8 — clamp-aware load dedup.
// x: [32,256,256,32] f32 NHWC ; theta: [32,6] f32 ; out: same shape.
// Layout (wavefront-optimal): 8 threads/pixel, one float4 each; 4 rows/thread.
// With random affine theta, ~half the output maps outside the input per axis;
// clamping then makes neighbor addresses identical (x0c==x1c / y0c==y1c).
// Warp-uniform votes skip the duplicate gathers entirely, cutting L1 read
// wavefronts ~40% in clamped regions with zero numeric change.

#define B_ 32
#define H_ 256
#define W_ 256
#define ROWS_ 4
#define STEP (2.0f / 255.0f)
#define FULL 0xFFFFFFFFu

__global__ __launch_bounds__(256) void stn_kernel(
    const float4* __restrict__ xf,
    const float* __restrict__ theta,
    float4* __restrict__ out)
{
    int gid = blockIdx.x * blockDim.x + threadIdx.x;   // [0, B*(H/4)*W*8)
    int cg  = gid & 7;                 // channel group
    int ox  = (gid >> 3) & 255;
    int oyq = (gid >> 11) & 63;        // quarter-row index
    int b   = gid >> 17;               // batch
    int oy  = oyq << 2;

    // affine params (uniform per batch, L1 broadcast)
    const float* t = theta + b * 6;
    float t0 = __ldg(t + 0), t1 = __ldg(t + 1), t2 = __ldg(t + 2);
    float t3 = __ldg(t + 3), t4 = __ldg(t + 4), t5 = __ldg(t + 5);

    float gx = -1.0f + (float)ox * STEP;
    int basep = b << 16;               // b * H*W
    int obase = ((basep + (oy << 8) + ox) << 3) + cg;

#pragma unroll
    for (int k = 0; k < ROWS_; k++) {
        float gy = -1.0f + (float)(oy + k) * STEP;

        // identical formula to reference: 0.5*(T·g + 1)*N, truncate toward zero
        float sx = 0.5f * (t0 * gx + t1 * gy + t2 + 1.0f) * (float)W_;
        float sy = 0.5f * (t3 * gx + t4 * gy + t5 + 1.0f) * (float)H_;

        int x0 = (int)sx;
        int y0 = (int)sy;

        int x0c = min(max(x0, 0), W_ - 1);
        int x1c = min(max(x0 + 1, 0), W_ - 1);
        int y0c = min(max(y0, 0), H_ - 1);
        int y1c = min(max(y0 + 1, 0), H_ - 1);

        float x0f = (float)x0c, x1f = (float)x1c;
        float y0f = (float)y0c, y1f = (float)y1c;

        float wa = (x1f - sx) * (y1f - sy);
        float wb = (x1f - sx) * (sy - y0f);
        float wc = (sx - x0f) * (y1f - sy);
        float wd = (sx - x0f) * (sy - y0f);

        // float4-unit indices; x1 column derived via dx (0 or 8)
        int dx = (x1c - x0c) << 3;
        int ia = ((basep + (y0c << 8) + x0c) << 3) + cg;
        int ib = ((basep + (y1c << 8) + x0c) << 3) + cg;

        // warp-uniform clamp detection: skip value-identical gathers
        bool ux = __all_sync(FULL, dx == 0);       // x clamped for whole warp
        bool uy = __all_sync(FULL, y1c == y0c);    // y clamped for whole warp

        float4 pa = __ldg(xf + ia);
        float4 pb, pc, pd;
        if (uy) { pb = pa; } else { pb = __ldg(xf + ib); }
        if (ux) { pc = pa; pd = pb; }
        else    { pc = __ldg(xf + ia + dx); pd = __ldg(xf + ib + dx); }

        float4 o;
        o.x = wa * pa.x + wb * pb.x + wc * pc.x + wd * pd.x;
        o.y = wa * pa.y + wb * pb.y + wc * pc.y + wd * pd.y;
        o.z = wa * pa.z + wb * pb.z + wc * pc.z + wd * pd.z;
        o.w = wa * pa.w + wb * pb.w + wc * pc.w + wd * pd.w;

        // streaming store: output is write-once, keep L2 for the gather set
        __stcs(out + obase + (k << 11), o);   // k * W_ * 8
    }
}

extern "C" void kernel_launch(void* const* d_in, const int* in_sizes, int n_in,
                              void* d_out, int out_size)
{
    const float4* x    = (const float4*)d_in[0];
    const float* theta = (const float*)d_in[1];
    float4* out = (float4*)d_out;

    int total_threads = B_ * (H_ / ROWS_) * W_ * 8;   // 4,194,304
    int block = 256;
    int grid = total_threads / block;                  // 16,384
    stn_kernel<<<grid, block>>>(x, theta, out);
}

// round 9
// speedup vs baseline: 1.1142x; 1.1142x over previous
#include <cuda_runtime.h>

// STN bilinear sampler, v9 — strip-level clamp dedup (vote once per 8 rows).
// x: [32,256,256,32] f32 NHWC ; theta: [32,6] f32 ; out: same shape.
// Layout: 8 threads/pixel, one float4 each (wavefront-optimal); 8 rows/thread.
// sx,sy are affine in the row index, so endpoint checks (rows 0 and 7) with a
// small margin classify the entire strip's clamp state. One warp vote + one
// uniform branch per strip selects a specialized body: 4/2/2/1 loads per row.
// Dedup'd loads are address-identical -> bit-exact vs always loading.

#define B_ 32
#define H_ 256
#define W_ 256
#define ROWS_ 8
#define STEP (2.0f / 255.0f)
#define FULL 0xFFFFFFFFu

struct Ctx {
    float t0, t1, t2, t3, t4, t5;
    float gx;
    int basep, cg, oy, obase;
};

// MODE bit0 = x-duplicated (x0c==x1c), bit1 = y-duplicated (y0c==y1c)
template <int MODE>
__device__ __forceinline__ void run_strip(const Ctx& c,
                                          const float4* __restrict__ xf,
                                          float4* __restrict__ out)
{
#pragma unroll
    for (int k = 0; k < ROWS_; k++) {
        float gy = -1.0f + (float)(c.oy + k) * STEP;

        // identical formula to reference: 0.5*(T·g + 1)*N, truncate toward zero
        float sx = 0.5f * (c.t0 * c.gx + c.t1 * gy + c.t2 + 1.0f) * (float)W_;
        float sy = 0.5f * (c.t3 * c.gx + c.t4 * gy + c.t5 + 1.0f) * (float)H_;

        int x0 = (int)sx;
        int y0 = (int)sy;

        int x0c = min(max(x0, 0), W_ - 1);
        int x1c = min(max(x0 + 1, 0), W_ - 1);
        int y0c = min(max(y0, 0), H_ - 1);
        int y1c = min(max(y0 + 1, 0), H_ - 1);

        float x0f = (float)x0c, x1f = (float)x1c;
        float y0f = (float)y0c, y1f = (float)y1c;

        float wa = (x1f - sx) * (y1f - sy);
        float wb = (x1f - sx) * (sy - y0f);
        float wc = (sx - x0f) * (y1f - sy);
        float wd = (sx - x0f) * (sy - y0f);

        int dx = (x1c - x0c) << 3;
        int ia = ((c.basep + (y0c << 8) + x0c) << 3) + c.cg;
        int ib = ((c.basep + (y1c << 8) + x0c) << 3) + c.cg;

        float4 pa = __ldg(xf + ia);
        float4 pb = (MODE & 2) ? pa : __ldg(xf + ib);
        float4 pc = (MODE & 1) ? pa : __ldg(xf + ia + dx);
        float4 pd = (MODE & 1) ? pb : ((MODE & 2) ? pc : __ldg(xf + ib + dx));

        float4 o;
        o.x = wa * pa.x + wb * pb.x + wc * pc.x + wd * pd.x;
        o.y = wa * pa.y + wb * pb.y + wc * pc.y + wd * pd.y;
        o.z = wa * pa.z + wb * pb.z + wc * pc.z + wd * pd.z;
        o.w = wa * pa.w + wb * pb.w + wc * pc.w + wd * pd.w;

        // streaming store: output is write-once, keep L2 for the gather set
        __stcs(out + c.obase + (k << 11), o);   // + k * W_ * 8
    }
}

__global__ __launch_bounds__(256) void stn_kernel(
    const float4* __restrict__ xf,
    const float* __restrict__ theta,
    float4* __restrict__ out)
{
    int gid = blockIdx.x * blockDim.x + threadIdx.x;   // [0, 2^21)
    Ctx c;
    c.cg  = gid & 7;
    int ox  = (gid >> 3) & 255;
    int oy8 = (gid >> 11) & 31;
    int b   = gid >> 16;
    c.oy = oy8 << 3;

    // theta via 3x LDG.64 (8B-aligned: b*24 bytes)
    const float2* t2p = (const float2*)(theta + b * 6);
    float2 q0 = __ldg(t2p + 0);
    float2 q1 = __ldg(t2p + 1);
    float2 q2 = __ldg(t2p + 2);
    c.t0 = q0.x; c.t1 = q0.y; c.t2 = q1.x;
    c.t3 = q1.y; c.t4 = q2.x; c.t5 = q2.y;

    c.gx = -1.0f + (float)ox * STEP;
    c.basep = b << 16;
    c.obase = ((c.basep + (c.oy << 8) + ox) << 3) + c.cg;

    // ---- strip classification via endpoint rows (sx,sy affine in oy) ----
    float gyA = -1.0f + (float)c.oy * STEP;
    float gyB = -1.0f + (float)(c.oy + ROWS_ - 1) * STEP;

    float sxA = 0.5f * (c.t0 * c.gx + c.t1 * gyA + c.t2 + 1.0f) * (float)W_;
    float syA = 0.5f * (c.t3 * c.gx + c.t4 * gyA + c.t5 + 1.0f) * (float)H_;
    float sxB = 0.5f * (c.t0 * c.gx + c.t1 * gyB + c.t2 + 1.0f) * (float)W_;
    float syB = 0.5f * (c.t3 * c.gx + c.t4 * gyB + c.t5 + 1.0f) * (float)H_;

    // conservative margins (fp rounding guard): claim dup only when certain
    bool xlo = (sxA <= -1.01f)  && (sxB <= -1.01f);
    bool xhi = (sxA >= 255.01f) && (sxB >= 255.01f);
    bool ylo = (syA <= -1.01f)  && (syB <= -1.01f);
    bool yhi = (syA >= 255.01f) && (syB >= 255.01f);

    bool ux = __all_sync(FULL, xlo) || __all_sync(FULL, xhi);
    bool uy = __all_sync(FULL, ylo) || __all_sync(FULL, yhi);

    if (ux) {
        if (uy) run_strip<3>(c, xf, out);
        else    run_strip<1>(c, xf, out);
    } else {
        if (uy) run_strip<2>(c, xf, out);
        else    run_strip<0>(c, xf, out);
    }
}

extern "C" void kernel_launch(void* const* d_in, const int* in_sizes, int n_in,
                              void* d_out, int out_size)
{
    const float4* x    = (const float4*)d_in[0];
    const float* theta = (const float*)d_in[1];
    float4* out = (float4*)d_out;

    int total_threads = B_ * (H_ / ROWS_) * W_ * 8;   // 2,097,152
    int block = 256;
    int grid = total_threads / block;                  // 8,192
    stn_kernel<<<grid, block>>>(x, theta, out);
}